// round 7
// baseline (speedup 1.0000x reference)
#include <cuda_runtime.h>

namespace {
constexpr int NX = 256, NY = 256, NZ = 128;
constexpr int NZ4 = NZ / 4, XS4 = NY * NZ4, FS4 = NX * XS4;
constexpr int BY = 8;                    // y rows per block

constexpr float CVc = 717.0f;
constexpr float MUc = 1.8e-5f, KTHc = 0.025f, Gc = 9.8f;
constexpr float Rg  = 287.0f;

constexpr double DXd = 1.0 / NX, DYd = 1.0 / NY, DZd = 1.0 / (NZ - 1);
constexpr float inv2dx = (float)(0.5 / DXd);
constexpr float inv2dy = (float)(0.5 / DYd);
constexpr float inv2dz = (float)(0.5 / DZd);
constexpr float invdx2 = (float)(1.0 / (DXd * DXd));
constexpr float invdy2 = (float)(1.0 / (DYd * DYd));
constexpr float invdz2 = (float)(1.0 / (DZd * DZd));
constexpr float kTco   = KTHc / CVc;

__device__ __forceinline__ float4 operator+(float4 a, float4 b){ return make_float4(a.x+b.x, a.y+b.y, a.z+b.z, a.w+b.w); }
__device__ __forceinline__ float4 operator-(float4 a, float4 b){ return make_float4(a.x-b.x, a.y-b.y, a.z-b.z, a.w-b.w); }
__device__ __forceinline__ float4 operator*(float4 a, float4 b){ return make_float4(a.x*b.x, a.y*b.y, a.z*b.z, a.w*b.w); }
__device__ __forceinline__ float4 operator*(float4 a, float s){ return make_float4(a.x*s, a.y*s, a.z*s, a.w*s); }
__device__ __forceinline__ float4 operator*(float s, float4 a){ return a * s; }

__device__ __forceinline__ float4 zm_of(float4 a){
    float p = __shfl_up_sync(0xffffffffu, a.w, 1);
    return make_float4(p, a.x, a.y, a.z);
}
__device__ __forceinline__ float4 zp_of(float4 a){
    float n = __shfl_down_sync(0xffffffffu, a.x, 1);
    return make_float4(a.y, a.z, a.w, n);
}

__device__ __forceinline__ float4 maskwall(float4 v, bool lo, bool hi){
    if (lo) v.x = 0.0f;
    if (hi) v.w = 0.0f;
    return v;
}

__global__ __launch_bounds__(256, 4)
void rb4s_kernel(const float4* __restrict__ s, float4* __restrict__ o)
{
    __shared__ float4 sm[6][BY + 2][32];           // 30720 B static

    const int lane = threadIdx.x;                   // z chunk (4 z per lane)
    const int ty   = threadIdx.y;                   // 0..7
    const int y    = (blockIdx.x << 3) | ty;
    const int x    = blockIdx.y;
    const int row  = ty + 1;

    const int rowc = y * NZ4 + lane;
    const int ic  = x * XS4 + rowc;
    const int ixm = ((x + NX - 1) & (NX - 1)) * XS4 + rowc;
    const int ixp = ((x + 1)      & (NX - 1)) * XS4 + rowc;

    const bool lo = (lane == 0);
    const bool hi = (lane == 31);

    // ---- stage this x-plane (centers + y halo) into smem ----
    const float4 uc = s[0 * FS4 + ic];
    const float4 vc = s[1 * FS4 + ic];
    const float4 wc = s[2 * FS4 + ic];
    sm[0][row][lane] = uc;
    sm[1][row][lane] = vc;
    sm[2][row][lane] = wc;
    sm[3][row][lane] = s[3 * FS4 + ic];
    sm[4][row][lane] = s[4 * FS4 + ic];
    sm[5][row][lane] = s[5 * FS4 + ic];
    if (ty == 0) {
        const int ih = x * XS4 + (((blockIdx.x << 3) + NY - 1) & (NY - 1)) * NZ4 + lane;
        #pragma unroll
        for (int f = 0; f < 6; f++) sm[f][0][lane] = s[f * FS4 + ih];
    }
    if (ty == BY - 1) {
        const int ih = x * XS4 + (((blockIdx.x << 3) + BY) & (NY - 1)) * NZ4 + lane;
        #pragma unroll
        for (int f = 0; f < 6; f++) sm[f][BY + 1][lane] = s[f * FS4 + ih];
    }
    __syncthreads();

    float4 rinv, dpdx, dpdy, dpdz;

    // ---- phase 1: rho & T -> rinv, dp*, dT, drou ----
    float4 uxm, uxp;                                // kept live into phase 2
    {
        const float4 rc  = sm[3][row][lane];
        rinv = make_float4(1.0f / rc.x, 1.0f / rc.y, 1.0f / rc.z, 1.0f / rc.w);
        const float4 rxm = s[3 * FS4 + ixm], rxp = s[3 * FS4 + ixp];
        const float4 rym = sm[3][row - 1][lane], ryp = sm[3][row + 1][lane];
        const float4 Tc  = sm[4][row][lane];
        const float4 Txm = s[4 * FS4 + ixm], Txp = s[4 * FS4 + ixp];
        const float4 Tym = sm[4][row - 1][lane], Typ = sm[4][row + 1][lane];
        const float4 rzm = zm_of(rc), rzp = zp_of(rc);
        const float4 Tzm = zm_of(Tc), Tzp = zp_of(Tc);

        dpdx = (rxp * Txp - rxm * Txm) * (Rg * inv2dx);
        dpdy = (ryp * Typ - rym * Tym) * (Rg * inv2dy);
        dpdz = (rzp * Tzp - rzm * Tzm) * (Rg * inv2dz);

        const float4 lapT = (Txp + Txm - Tc * 2.0f) * invdx2 + (Typ + Tym - Tc * 2.0f) * invdy2 + (Tzp + Tzm - Tc * 2.0f) * invdz2;
        const float4 advT = uc * ((Txp - Txm) * inv2dx) + vc * ((Typ - Tym) * inv2dy) + wc * ((Tzp - Tzm) * inv2dz);
        __stcs(&o[4 * FS4 + ic], maskwall((lapT * kTco) * rinv - advT, lo, hi));

        uxm = s[0 * FS4 + ixm]; uxp = s[0 * FS4 + ixp];
        __stcs(&o[3 * FS4 + ic], (rxm * uxm - rxp * uxp) * inv2dx);
    }

    // ---- phase 2: u ----
    {
        const float4 uym = sm[0][row - 1][lane], uyp = sm[0][row + 1][lane];
        const float4 uzm = zm_of(uc), uzp = zp_of(uc);
        const float4 lapU = (uxp + uxm - uc * 2.0f) * invdx2 + (uyp + uym - uc * 2.0f) * invdy2 + (uzp + uzm - uc * 2.0f) * invdz2;
        const float4 advU = uc * ((uxp - uxm) * inv2dx) + vc * ((uyp - uym) * inv2dy) + wc * ((uzp - uzm) * inv2dz);
        __stcs(&o[0 * FS4 + ic], maskwall((lapU * MUc - dpdx) * rinv - advU, lo, hi));
    }

    // ---- phase 3: v ----
    {
        const float4 vxm = s[1 * FS4 + ixm], vxp = s[1 * FS4 + ixp];
        const float4 vym = sm[1][row - 1][lane], vyp = sm[1][row + 1][lane];
        const float4 vzm = zm_of(vc), vzp = zp_of(vc);
        const float4 lapV = (vxp + vxm - vc * 2.0f) * invdx2 + (vyp + vym - vc * 2.0f) * invdy2 + (vzp + vzm - vc * 2.0f) * invdz2;
        const float4 advV = uc * ((vxp - vxm) * inv2dx) + vc * ((vyp - vym) * inv2dy) + wc * ((vzp - vzm) * inv2dz);
        __stcs(&o[1 * FS4 + ic], maskwall((lapV * MUc - dpdy) * rinv - advV, lo, hi));
    }

    // ---- phase 4: w  ((-G*rho)/rho == -G) ----
    {
        const float4 wxm = s[2 * FS4 + ixm], wxp = s[2 * FS4 + ixp];
        const float4 wym = sm[2][row - 1][lane], wyp = sm[2][row + 1][lane];
        const float4 wzm = zm_of(wc), wzp = zp_of(wc);
        const float4 lapW = (wxp + wxm - wc * 2.0f) * invdx2 + (wyp + wym - wc * 2.0f) * invdy2 + (wzp + wzm - wc * 2.0f) * invdz2;
        const float4 advW = uc * ((wxp - wxm) * inv2dx) + vc * ((wyp - wym) * inv2dy) + wc * ((wzp - wzm) * inv2dz);
        float4 dw = (lapW * MUc - dpdz) * rinv - advW;
        dw = make_float4(dw.x - Gc, dw.y - Gc, dw.z - Gc, dw.w - Gc);
        __stcs(&o[2 * FS4 + ic], maskwall(dw, lo, hi));
    }

    // ---- phase 5: c (one-sided z at walls, NOT masked) ----
    {
        const float4 cc  = sm[5][row][lane];
        const float4 cxm = s[5 * FS4 + ixm], cxp = s[5 * FS4 + ixp];
        const float4 cym = sm[5][row - 1][lane], cyp = sm[5][row + 1][lane];
        const float4 czm = zm_of(cc), czp = zp_of(cc);

        float4 dcdz = (czp - czm) * inv2dz;
        if (lo) dcdz.x = (-3.0f * cc.x + 4.0f * cc.y - cc.z) * inv2dz;
        if (hi) dcdz.w = ( 3.0f * cc.w - 4.0f * cc.z + cc.y) * inv2dz;

        const float4 advC = uc * ((cxp - cxm) * inv2dx) + vc * ((cyp - cym) * inv2dy) + wc * dcdz;
        __stcs(&o[5 * FS4 + ic], make_float4(-advC.x, -advC.y, -advC.z, -advC.w));
    }
}
} // namespace

extern "C" void kernel_launch(void* const* d_in, const int* in_sizes, int n_in,
                              void* d_out, int out_size)
{
    const float4* s = (const float4*)d_in[0];
    float4* o = (float4*)d_out;
    dim3 block(32, BY, 1);            // 256 threads
    dim3 grid(NY / BY, NX, 1);        // 32 × 256 blocks
    rb4s_kernel<<<grid, block>>>(s, o);
}

// round 8
// speedup vs baseline: 1.3783x; 1.3783x over previous
#include <cuda_runtime.h>

namespace {
constexpr int NX = 256, NY = 256, NZ = 128;
constexpr int NZ4 = NZ / 4, XS4 = NY * NZ4, FS4 = NX * XS4;

constexpr float CVc = 717.0f;
constexpr float MUc = 1.8e-5f, KTHc = 0.025f, Gc = 9.8f;
constexpr float Rg  = 287.0f;

constexpr double DXd = 1.0 / NX, DYd = 1.0 / NY, DZd = 1.0 / (NZ - 1);
constexpr float inv2dx = (float)(0.5 / DXd);
constexpr float inv2dy = (float)(0.5 / DYd);
constexpr float inv2dz = (float)(0.5 / DZd);
constexpr float invdx2 = (float)(1.0 / (DXd * DXd));
constexpr float invdy2 = (float)(1.0 / (DYd * DYd));
constexpr float invdz2 = (float)(1.0 / (DZd * DZd));
constexpr float kTco   = KTHc / CVc;

__device__ __forceinline__ float4 operator+(float4 a, float4 b){ return make_float4(a.x+b.x, a.y+b.y, a.z+b.z, a.w+b.w); }
__device__ __forceinline__ float4 operator-(float4 a, float4 b){ return make_float4(a.x-b.x, a.y-b.y, a.z-b.z, a.w-b.w); }
__device__ __forceinline__ float4 operator*(float4 a, float4 b){ return make_float4(a.x*b.x, a.y*b.y, a.z*b.z, a.w*b.w); }
__device__ __forceinline__ float4 operator*(float4 a, float s){ return make_float4(a.x*s, a.y*s, a.z*s, a.w*s); }
__device__ __forceinline__ float4 operator*(float s, float4 a){ return a * s; }

__device__ __forceinline__ float4 zm_of(float4 a){
    float p = __shfl_up_sync(0xffffffffu, a.w, 1);
    return make_float4(p, a.x, a.y, a.z);
}
__device__ __forceinline__ float4 zp_of(float4 a){
    float n = __shfl_down_sync(0xffffffffu, a.x, 1);
    return make_float4(a.y, a.z, a.w, n);
}
__device__ __forceinline__ float4 inv4(float4 a){
    return make_float4(1.0f/a.x, 1.0f/a.y, 1.0f/a.z, 1.0f/a.w);
}
__device__ __forceinline__ float4 maskwall(float4 v, bool lo, bool hi){
    if (lo) v.x = 0.0f;
    if (hi) v.w = 0.0f;
    return v;
}

__global__ __launch_bounds__(256, 2)
void rbx2_kernel(const float4* __restrict__ s, float4* __restrict__ o)
{
    const int lane = threadIdx.x;                     // z chunk (4 z per lane)
    const int y  = (blockIdx.x << 3) | threadIdx.y;   // 8 y rows per block
    const int x0 = blockIdx.y << 1;                   // 2 x-points per thread

    const int bxm = ((x0 + NX - 1) & (NX - 1)) * XS4;
    const int b0  = x0 * XS4;
    const int b1  = (x0 + 1) * XS4;
    const int bxq = ((x0 + 2) & (NX - 1)) * XS4;

    const int rc_  = y * NZ4 + lane;
    const int rym_ = ((y + NY - 1) & (NY - 1)) * NZ4 + lane;
    const int ryp_ = ((y + 1)      & (NY - 1)) * NZ4 + lane;

    const bool lo = (lane == 0);
    const bool hi = (lane == 31);

    // ================= phase 1a: rho, T -> p, dp*, rinv, drou, u planes =================
    float4 u_xm, u0, u1, u_xq;                 // persist into u phase
    float4 rinv0, rinv1, Tc0, Tc1;
    float4 dpdx0, dpdx1, dpdy0, dpdy1, dpdz0, dpdz1;
    {
        const float4 r_xm = s[3*FS4 + bxm + rc_], r_0 = s[3*FS4 + b0 + rc_];
        const float4 r_1  = s[3*FS4 + b1  + rc_], r_xq = s[3*FS4 + bxq + rc_];
        const float4 T_xm = s[4*FS4 + bxm + rc_];
        Tc0 = s[4*FS4 + b0 + rc_];
        Tc1 = s[4*FS4 + b1 + rc_];
        const float4 T_xq = s[4*FS4 + bxq + rc_];

        u_xm = s[0*FS4 + bxm + rc_]; u0 = s[0*FS4 + b0 + rc_];
        u1   = s[0*FS4 + b1  + rc_]; u_xq = s[0*FS4 + bxq + rc_];

        // continuity (x-flux only)
        __stcs(&o[3*FS4 + b0 + rc_], (r_xm * u_xm - r_1 * u1) * inv2dx);
        __stcs(&o[3*FS4 + b1 + rc_], (r_0  * u0   - r_xq * u_xq) * inv2dx);

        rinv0 = inv4(r_0);
        rinv1 = inv4(r_1);

        const float4 p_xm = (Rg) * r_xm * T_xm;
        const float4 p0   = (Rg) * r_0  * Tc0;
        const float4 p1   = (Rg) * r_1  * Tc1;
        const float4 p_xq = (Rg) * r_xq * T_xq;

        dpdx0 = (p1   - p_xm) * inv2dx;
        dpdx1 = (p_xq - p0)   * inv2dx;
        dpdz0 = (zp_of(p0) - zm_of(p0)) * inv2dz;
        dpdz1 = (zp_of(p1) - zm_of(p1)) * inv2dz;

        // y-pressure (load r,T at y-neighbors, form p, drop)
        float4 ra = s[3*FS4 + b0 + rym_], Ta = s[4*FS4 + b0 + rym_];
        float4 rb = s[3*FS4 + b0 + ryp_], Tb = s[4*FS4 + b0 + ryp_];
        dpdy0 = (rb * Tb - ra * Ta) * (Rg * inv2dy);
        ra = s[3*FS4 + b1 + rym_]; Ta = s[4*FS4 + b1 + rym_];
        rb = s[3*FS4 + b1 + ryp_]; Tb = s[4*FS4 + b1 + ryp_];
        dpdy1 = (rb * Tb - ra * Ta) * (Rg * inv2dy);
    }

    // ================= phase 1b: dT (reload T neighbors — L1 hot) + v,w centers ========
    float4 vc0, vc1, wc0, wc1;                 // persist as advection velocities
    {
        vc0 = s[1*FS4 + b0 + rc_]; vc1 = s[1*FS4 + b1 + rc_];
        wc0 = s[2*FS4 + b0 + rc_]; wc1 = s[2*FS4 + b1 + rc_];

        const float4 Txm  = s[4*FS4 + bxm + rc_], Txq  = s[4*FS4 + bxq + rc_];
        const float4 Tym0 = s[4*FS4 + b0 + rym_], Typ0 = s[4*FS4 + b0 + ryp_];
        const float4 Tym1 = s[4*FS4 + b1 + rym_], Typ1 = s[4*FS4 + b1 + ryp_];
        const float4 Tzm0 = zm_of(Tc0), Tzp0 = zp_of(Tc0);
        const float4 Tzm1 = zm_of(Tc1), Tzp1 = zp_of(Tc1);

        const float4 lapT0 = (Tc1 + Txm - Tc0*2.0f)*invdx2 + (Typ0 + Tym0 - Tc0*2.0f)*invdy2 + (Tzp0 + Tzm0 - Tc0*2.0f)*invdz2;
        const float4 advT0 = u0*((Tc1 - Txm)*inv2dx) + vc0*((Typ0 - Tym0)*inv2dy) + wc0*((Tzp0 - Tzm0)*inv2dz);
        __stcs(&o[4*FS4 + b0 + rc_], maskwall((lapT0 * kTco) * rinv0 - advT0, lo, hi));

        const float4 lapT1 = (Txq + Tc0 - Tc1*2.0f)*invdx2 + (Typ1 + Tym1 - Tc1*2.0f)*invdy2 + (Tzp1 + Tzm1 - Tc1*2.0f)*invdz2;
        const float4 advT1 = u1*((Txq - Tc0)*inv2dx) + vc1*((Typ1 - Tym1)*inv2dy) + wc1*((Tzp1 - Tzm1)*inv2dz);
        __stcs(&o[4*FS4 + b1 + rc_], maskwall((lapT1 * kTco) * rinv1 - advT1, lo, hi));
    }

    // ================= phase 2: u =================
    {
        const float4 uym0 = s[0*FS4 + b0 + rym_], uyp0 = s[0*FS4 + b0 + ryp_];
        const float4 uym1 = s[0*FS4 + b1 + rym_], uyp1 = s[0*FS4 + b1 + ryp_];
        const float4 uzm0 = zm_of(u0), uzp0 = zp_of(u0);
        const float4 uzm1 = zm_of(u1), uzp1 = zp_of(u1);

        const float4 lapU0 = (u1 + u_xm - u0*2.0f)*invdx2 + (uyp0 + uym0 - u0*2.0f)*invdy2 + (uzp0 + uzm0 - u0*2.0f)*invdz2;
        const float4 advU0 = u0*((u1 - u_xm)*inv2dx) + vc0*((uyp0 - uym0)*inv2dy) + wc0*((uzp0 - uzm0)*inv2dz);
        __stcs(&o[0*FS4 + b0 + rc_], maskwall((lapU0 * MUc - dpdx0) * rinv0 - advU0, lo, hi));

        const float4 lapU1 = (u_xq + u0 - u1*2.0f)*invdx2 + (uyp1 + uym1 - u1*2.0f)*invdy2 + (uzp1 + uzm1 - u1*2.0f)*invdz2;
        const float4 advU1 = u1*((u_xq - u0)*inv2dx) + vc1*((uyp1 - uym1)*inv2dy) + wc1*((uzp1 - uzm1)*inv2dz);
        __stcs(&o[0*FS4 + b1 + rc_], maskwall((lapU1 * MUc - dpdx1) * rinv1 - advU1, lo, hi));
    }

    // ================= phase 3: v =================
    {
        const float4 v_xm = s[1*FS4 + bxm + rc_], v_xq = s[1*FS4 + bxq + rc_];
        const float4 vym0 = s[1*FS4 + b0 + rym_], vyp0 = s[1*FS4 + b0 + ryp_];
        const float4 vym1 = s[1*FS4 + b1 + rym_], vyp1 = s[1*FS4 + b1 + ryp_];
        const float4 vzm0 = zm_of(vc0), vzp0 = zp_of(vc0);
        const float4 vzm1 = zm_of(vc1), vzp1 = zp_of(vc1);

        const float4 lapV0 = (vc1 + v_xm - vc0*2.0f)*invdx2 + (vyp0 + vym0 - vc0*2.0f)*invdy2 + (vzp0 + vzm0 - vc0*2.0f)*invdz2;
        const float4 advV0 = u0*((vc1 - v_xm)*inv2dx) + vc0*((vyp0 - vym0)*inv2dy) + wc0*((vzp0 - vzm0)*inv2dz);
        __stcs(&o[1*FS4 + b0 + rc_], maskwall((lapV0 * MUc - dpdy0) * rinv0 - advV0, lo, hi));

        const float4 lapV1 = (v_xq + vc0 - vc1*2.0f)*invdx2 + (vyp1 + vym1 - vc1*2.0f)*invdy2 + (vzp1 + vzm1 - vc1*2.0f)*invdz2;
        const float4 advV1 = u1*((v_xq - vc0)*inv2dx) + vc1*((vyp1 - vym1)*inv2dy) + wc1*((vzp1 - vzm1)*inv2dz);
        __stcs(&o[1*FS4 + b1 + rc_], maskwall((lapV1 * MUc - dpdy1) * rinv1 - advV1, lo, hi));
    }

    // ================= phase 4: w  ((-G*rho)/rho == -G) =================
    {
        const float4 w_xm = s[2*FS4 + bxm + rc_], w_xq = s[2*FS4 + bxq + rc_];
        const float4 wym0 = s[2*FS4 + b0 + rym_], wyp0 = s[2*FS4 + b0 + ryp_];
        const float4 wym1 = s[2*FS4 + b1 + rym_], wyp1 = s[2*FS4 + b1 + ryp_];
        const float4 wzm0 = zm_of(wc0), wzp0 = zp_of(wc0);
        const float4 wzm1 = zm_of(wc1), wzp1 = zp_of(wc1);

        const float4 lapW0 = (wc1 + w_xm - wc0*2.0f)*invdx2 + (wyp0 + wym0 - wc0*2.0f)*invdy2 + (wzp0 + wzm0 - wc0*2.0f)*invdz2;
        const float4 advW0 = u0*((wc1 - w_xm)*inv2dx) + vc0*((wyp0 - wym0)*inv2dy) + wc0*((wzp0 - wzm0)*inv2dz);
        float4 dw0 = (lapW0 * MUc - dpdz0) * rinv0 - advW0;
        dw0 = make_float4(dw0.x - Gc, dw0.y - Gc, dw0.z - Gc, dw0.w - Gc);
        __stcs(&o[2*FS4 + b0 + rc_], maskwall(dw0, lo, hi));

        const float4 lapW1 = (w_xq + wc0 - wc1*2.0f)*invdx2 + (wyp1 + wym1 - wc1*2.0f)*invdy2 + (wzp1 + wzm1 - wc1*2.0f)*invdz2;
        const float4 advW1 = u1*((w_xq - wc0)*inv2dx) + vc1*((wyp1 - wym1)*inv2dy) + wc1*((wzp1 - wzm1)*inv2dz);
        float4 dw1 = (lapW1 * MUc - dpdz1) * rinv1 - advW1;
        dw1 = make_float4(dw1.x - Gc, dw1.y - Gc, dw1.z - Gc, dw1.w - Gc);
        __stcs(&o[2*FS4 + b1 + rc_], maskwall(dw1, lo, hi));
    }

    // ================= phase 5: c (one-sided z at walls, NOT masked) =================
    {
        const float4 c_xm = s[5*FS4 + bxm + rc_], c0 = s[5*FS4 + b0 + rc_];
        const float4 c1   = s[5*FS4 + b1  + rc_], c_xq = s[5*FS4 + bxq + rc_];
        const float4 cym0 = s[5*FS4 + b0 + rym_], cyp0 = s[5*FS4 + b0 + ryp_];
        const float4 cym1 = s[5*FS4 + b1 + rym_], cyp1 = s[5*FS4 + b1 + ryp_];

        const float4 czm0 = zm_of(c0), czp0 = zp_of(c0);
        const float4 czm1 = zm_of(c1), czp1 = zp_of(c1);

        float4 dcdz0 = (czp0 - czm0) * inv2dz;
        float4 dcdz1 = (czp1 - czm1) * inv2dz;
        if (lo) {
            dcdz0.x = (-3.0f * c0.x + 4.0f * c0.y - c0.z) * inv2dz;
            dcdz1.x = (-3.0f * c1.x + 4.0f * c1.y - c1.z) * inv2dz;
        }
        if (hi) {
            dcdz0.w = ( 3.0f * c0.w - 4.0f * c0.z + c0.y) * inv2dz;
            dcdz1.w = ( 3.0f * c1.w - 4.0f * c1.z + c1.y) * inv2dz;
        }

        const float4 advC0 = u0*((c1 - c_xm)*inv2dx) + vc0*((cyp0 - cym0)*inv2dy) + wc0*dcdz0;
        __stcs(&o[5*FS4 + b0 + rc_], make_float4(-advC0.x, -advC0.y, -advC0.z, -advC0.w));
        const float4 advC1 = u1*((c_xq - c0)*inv2dx) + vc1*((cyp1 - cym1)*inv2dy) + wc1*dcdz1;
        __stcs(&o[5*FS4 + b1 + rc_], make_float4(-advC1.x, -advC1.y, -advC1.z, -advC1.w));
    }
}
} // namespace

extern "C" void kernel_launch(void* const* d_in, const int* in_sizes, int n_in,
                              void* d_out, int out_size)
{
    const float4* s = (const float4*)d_in[0];
    float4* o = (float4*)d_out;
    dim3 block(32, 8, 1);               // 256 threads
    dim3 grid(NY / 8, NX / 2, 1);       // 32 × 128 blocks, 2 x-points per thread
    rbx2_kernel<<<grid, block>>>(s, o);
}